// round 1
// baseline (speedup 1.0000x reference)
#include <cuda_runtime.h>
#include <cstdint>

// ---------------------------------------------------------------------------
// Problem constants
//   B=8, S=512, D_MODEL=1024, H=16, DK=DV=64, BH=128
// ---------------------------------------------------------------------------
#define BB   8
#define SS_  512
#define DM   1024
#define HH   16
#define DKV  64
#define BH   128
#define SCALE 0.125f   // 1/sqrt(64)

// ---------------------------------------------------------------------------
// Scratch (device globals -- no allocation allowed in kernel_launch)
// ---------------------------------------------------------------------------
__device__ float g_q[(size_t)BH * SS_ * DKV];     // [bh, s, d]   16 MB
__device__ float g_k[(size_t)BH * SS_ * DKV];
__device__ float g_v[(size_t)BH * SS_ * DKV];
__device__ float g_sc[(size_t)BH * SS_ * SS_];    // [bh, i, j]   134 MB
__device__ float g_ctx[(size_t)BB * SS_ * DM];    // [b, s, h*64+d] 16 MB

// ===========================================================================
// Kernel 1: QKV projection.  X[4096,1024] @ W[1024,1024] + b
// 128x128 block tile, BK=8, 256 threads, 8x8 per thread.
// Output scattered into [bh, s, d] layout.
// ===========================================================================
__global__ __launch_bounds__(256) void k_proj(
    const float* __restrict__ X,
    const float* __restrict__ Wq, const float* __restrict__ bq,
    const float* __restrict__ Wk, const float* __restrict__ bk,
    const float* __restrict__ Wv, const float* __restrict__ bv)
{
    const float* W; const float* bias; float* out;
    if (blockIdx.z == 0)      { W = Wq; bias = bq; out = g_q; }
    else if (blockIdx.z == 1) { W = Wk; bias = bk; out = g_k; }
    else                      { W = Wv; bias = bv; out = g_v; }

    __shared__ float As[8][132];   // [k][m]
    __shared__ float Bs[8][132];   // [k][n]

    const int tid = threadIdx.x;
    const int m0 = blockIdx.x * 128;
    const int n0 = blockIdx.y * 128;

    const int ar = tid >> 1, ac = (tid & 1) * 4;   // A load: row, k-col
    const int br = tid >> 5, bc = (tid & 31) * 4;  // B load
    const int tx = tid & 15, ty = tid >> 4;

    float acc[8][8];
#pragma unroll
    for (int i = 0; i < 8; i++)
#pragma unroll
        for (int j = 0; j < 8; j++) acc[i][j] = 0.f;

    for (int k0 = 0; k0 < DM; k0 += 8) {
        float4 av = *(const float4*)(X + (size_t)(m0 + ar) * DM + k0 + ac);
        As[ac + 0][ar] = av.x; As[ac + 1][ar] = av.y;
        As[ac + 2][ar] = av.z; As[ac + 3][ar] = av.w;
        *(float4*)(&Bs[br][bc]) =
            *(const float4*)(W + (size_t)(k0 + br) * DM + n0 + bc);
        __syncthreads();
#pragma unroll
        for (int k = 0; k < 8; k++) {
            float a[8], b[8];
            *(float4*)(a)     = *(float4*)(&As[k][ty * 4]);
            *(float4*)(a + 4) = *(float4*)(&As[k][64 + ty * 4]);
            *(float4*)(b)     = *(float4*)(&Bs[k][tx * 4]);
            *(float4*)(b + 4) = *(float4*)(&Bs[k][64 + tx * 4]);
#pragma unroll
            for (int i = 0; i < 8; i++)
#pragma unroll
                for (int j = 0; j < 8; j++) acc[i][j] += a[i] * b[j];
        }
        __syncthreads();
    }

#pragma unroll
    for (int i = 0; i < 8; i++) {
        int row = m0 + ((i < 4) ? (ty * 4 + i) : (64 + ty * 4 + i - 4));
        int b_ = row >> 9, s_ = row & 511;
#pragma unroll
        for (int jh = 0; jh < 2; jh++) {
            int col = n0 + jh * 64 + tx * 4;
            int h_ = col >> 6, d_ = col & 63;
            float4 o;
            o.x = acc[i][jh * 4 + 0] + bias[col + 0];
            o.y = acc[i][jh * 4 + 1] + bias[col + 1];
            o.z = acc[i][jh * 4 + 2] + bias[col + 2];
            o.w = acc[i][jh * 4 + 3] + bias[col + 3];
            *(float4*)(out + ((size_t)((b_ * HH + h_) * SS_ + s_)) * DKV + d_) = o;
        }
    }
}

// ===========================================================================
// Kernel 2: edge-key scores.  For fixed i:
//   g_sc[bh, i, j] = SCALE * sum_d q[bh,i,d] * EK[i,j,d]
// Block = (i, j-tile of 128), output tile [128 bh x 128 j], K=64.
// ===========================================================================
__global__ __launch_bounds__(256) void k_edge_scores(const float* __restrict__ EK)
{
    const int i  = blockIdx.y;
    const int j0 = blockIdx.x * 128;
    const int tid = threadIdx.x;
    const int tx = tid & 15, ty = tid >> 4;

    __shared__ float Qs[128][68];   // [bh][d]
    __shared__ float Es[16][132];   // [d][j]  per 16-d chunk

    {
        int d4 = (tid & 15) * 4;
#pragma unroll
        for (int r = 0; r < 8; r++) {
            int bh = r * 16 + (tid >> 4);
            *(float4*)(&Qs[bh][d4]) =
                *(const float4*)(g_q + ((size_t)bh * SS_ + i) * DKV + d4);
        }
    }

    float acc[8][8];
#pragma unroll
    for (int a = 0; a < 8; a++)
#pragma unroll
        for (int b = 0; b < 8; b++) acc[a][b] = 0.f;

    const int er = tid >> 1, ep = tid & 1;

    for (int dk0 = 0; dk0 < 64; dk0 += 16) {
        __syncthreads();
        const float* Erow = EK + ((size_t)i * SS_ + j0 + er) * DKV + dk0 + ep * 8;
        float4 e0 = *(const float4*)(Erow);
        float4 e1 = *(const float4*)(Erow + 4);
        Es[ep * 8 + 0][er] = e0.x; Es[ep * 8 + 1][er] = e0.y;
        Es[ep * 8 + 2][er] = e0.z; Es[ep * 8 + 3][er] = e0.w;
        Es[ep * 8 + 4][er] = e1.x; Es[ep * 8 + 5][er] = e1.y;
        Es[ep * 8 + 6][er] = e1.z; Es[ep * 8 + 7][er] = e1.w;
        __syncthreads();
#pragma unroll
        for (int k = 0; k < 16; k++) {
            float b[8];
            *(float4*)(b)     = *(float4*)(&Es[k][tx * 4]);
            *(float4*)(b + 4) = *(float4*)(&Es[k][64 + tx * 4]);
            float a[8];
#pragma unroll
            for (int ii = 0; ii < 8; ii++) {
                int bh = (ii < 4) ? (ty * 4 + ii) : (64 + ty * 4 + ii - 4);
                a[ii] = Qs[bh][dk0 + k];
            }
#pragma unroll
            for (int ii = 0; ii < 8; ii++)
#pragma unroll
                for (int jj = 0; jj < 8; jj++) acc[ii][jj] += a[ii] * b[jj];
        }
    }

#pragma unroll
    for (int ii = 0; ii < 8; ii++) {
        int bh = (ii < 4) ? (ty * 4 + ii) : (64 + ty * 4 + ii - 4);
        float* dst = g_sc + ((size_t)bh * SS_ + i) * SS_ + j0;
#pragma unroll
        for (int jh = 0; jh < 2; jh++) {
            float4 o;
            o.x = acc[ii][jh * 4 + 0] * SCALE;
            o.y = acc[ii][jh * 4 + 1] * SCALE;
            o.z = acc[ii][jh * 4 + 2] * SCALE;
            o.w = acc[ii][jh * 4 + 3] * SCALE;
            *(float4*)(dst + jh * 64 + tx * 4) = o;
        }
    }
}

// ===========================================================================
// Kernel 3: content scores:  g_sc += SCALE * q[bh] @ k[bh]^T + bias
// Block = (j-tile, i-tile, bh); tile 128x128, K=64 in chunks of 16.
// ===========================================================================
__global__ __launch_bounds__(256) void k_content_scores(const float* __restrict__ bias)
{
    const int bh = blockIdx.z;
    const int i0 = blockIdx.y * 128;
    const int j0 = blockIdx.x * 128;
    const int tid = threadIdx.x;
    const int tx = tid & 15, ty = tid >> 4;
    const int r_ = tid >> 1, p_ = tid & 1;

    __shared__ float As[16][132];   // [d][i]
    __shared__ float Bs[16][132];   // [d][j]

    const float* qb = g_q + (size_t)bh * SS_ * DKV;
    const float* kb = g_k + (size_t)bh * SS_ * DKV;

    float acc[8][8];
#pragma unroll
    for (int a = 0; a < 8; a++)
#pragma unroll
        for (int b = 0; b < 8; b++) acc[a][b] = 0.f;

    for (int dk0 = 0; dk0 < 64; dk0 += 16) {
        __syncthreads();
        {
            const float* src = qb + (size_t)(i0 + r_) * DKV + dk0 + p_ * 8;
            float4 a0 = *(const float4*)(src);
            float4 a1 = *(const float4*)(src + 4);
            As[p_ * 8 + 0][r_] = a0.x; As[p_ * 8 + 1][r_] = a0.y;
            As[p_ * 8 + 2][r_] = a0.z; As[p_ * 8 + 3][r_] = a0.w;
            As[p_ * 8 + 4][r_] = a1.x; As[p_ * 8 + 5][r_] = a1.y;
            As[p_ * 8 + 6][r_] = a1.z; As[p_ * 8 + 7][r_] = a1.w;
        }
        {
            const float* src = kb + (size_t)(j0 + r_) * DKV + dk0 + p_ * 8;
            float4 b0 = *(const float4*)(src);
            float4 b1 = *(const float4*)(src + 4);
            Bs[p_ * 8 + 0][r_] = b0.x; Bs[p_ * 8 + 1][r_] = b0.y;
            Bs[p_ * 8 + 2][r_] = b0.z; Bs[p_ * 8 + 3][r_] = b0.w;
            Bs[p_ * 8 + 4][r_] = b1.x; Bs[p_ * 8 + 5][r_] = b1.y;
            Bs[p_ * 8 + 6][r_] = b1.z; Bs[p_ * 8 + 7][r_] = b1.w;
        }
        __syncthreads();
#pragma unroll
        for (int k = 0; k < 16; k++) {
            float a[8], b[8];
            *(float4*)(a)     = *(float4*)(&As[k][ty * 4]);
            *(float4*)(a + 4) = *(float4*)(&As[k][64 + ty * 4]);
            *(float4*)(b)     = *(float4*)(&Bs[k][tx * 4]);
            *(float4*)(b + 4) = *(float4*)(&Bs[k][64 + tx * 4]);
#pragma unroll
            for (int ii = 0; ii < 8; ii++)
#pragma unroll
                for (int jj = 0; jj < 8; jj++) acc[ii][jj] += a[ii] * b[jj];
        }
    }

#pragma unroll
    for (int ii = 0; ii < 8; ii++) {
        int row = i0 + ((ii < 4) ? (ty * 4 + ii) : (64 + ty * 4 + ii - 4));
        size_t base = ((size_t)bh * SS_ + row) * SS_ + j0;
#pragma unroll
        for (int jh = 0; jh < 2; jh++) {
            int c = jh * 64 + tx * 4;
            float4 prev = *(const float4*)(g_sc + base + c);
            float4 bz   = *(const float4*)(bias + base + c);
            float4 o;
            o.x = acc[ii][jh * 4 + 0] * SCALE + prev.x + bz.x;
            o.y = acc[ii][jh * 4 + 1] * SCALE + prev.y + bz.y;
            o.z = acc[ii][jh * 4 + 2] * SCALE + prev.z + bz.z;
            o.w = acc[ii][jh * 4 + 3] * SCALE + prev.w + bz.w;
            *(float4*)(g_sc + base + c) = o;
        }
    }
}

// ===========================================================================
// Kernel 4: row softmax over j.  One warp per 512-float row.
// ===========================================================================
__global__ __launch_bounds__(256) void k_softmax()
{
    const int warp = threadIdx.x >> 5, lane = threadIdx.x & 31;
    const size_t row = (size_t)blockIdx.x * 8 + warp;
    float* p = g_sc + row * SS_;

    float4 v[4];
    float mx = -1e30f;
#pragma unroll
    for (int w = 0; w < 4; w++) {
        v[w] = *(const float4*)(p + w * 128 + lane * 4);
        mx = fmaxf(mx, fmaxf(fmaxf(v[w].x, v[w].y), fmaxf(v[w].z, v[w].w)));
    }
#pragma unroll
    for (int o = 16; o > 0; o >>= 1) mx = fmaxf(mx, __shfl_xor_sync(~0u, mx, o));

    float sum = 0.f;
#pragma unroll
    for (int w = 0; w < 4; w++) {
        v[w].x = __expf(v[w].x - mx); v[w].y = __expf(v[w].y - mx);
        v[w].z = __expf(v[w].z - mx); v[w].w = __expf(v[w].w - mx);
        sum += v[w].x + v[w].y + v[w].z + v[w].w;
    }
#pragma unroll
    for (int o = 16; o > 0; o >>= 1) sum += __shfl_xor_sync(~0u, sum, o);
    float r = 1.f / sum;
#pragma unroll
    for (int w = 0; w < 4; w++) {
        v[w].x *= r; v[w].y *= r; v[w].z *= r; v[w].w *= r;
        *(float4*)(p + w * 128 + lane * 4) = v[w];
    }
}

// ===========================================================================
// Kernel 5: content context:  ctx[b,s,h*64+d] = W[bh] @ V[bh]
// Block = (i-tile of 128, bh); tile 128x64, K=512 in chunks of 16.
// ===========================================================================
__global__ __launch_bounds__(256) void k_ctx_content()
{
    const int bh = blockIdx.y;
    const int i0 = blockIdx.x * 128;
    const int tid = threadIdx.x;
    const int tx = tid & 15, ty = tid >> 4;
    const int r_ = tid >> 1, p_ = tid & 1;
    const int vr = tid >> 4, vd = (tid & 15) * 4;

    __shared__ float As[16][132];   // [j][i]
    __shared__ float Bs[16][68];    // [j][d]

    const float* wb = g_sc + ((size_t)bh * SS_ + i0) * SS_;
    const float* vb = g_v + (size_t)bh * SS_ * DKV;

    float acc[8][4];
#pragma unroll
    for (int a = 0; a < 8; a++)
#pragma unroll
        for (int b = 0; b < 4; b++) acc[a][b] = 0.f;

    for (int k0 = 0; k0 < SS_; k0 += 16) {
        __syncthreads();
        {
            const float* src = wb + (size_t)r_ * SS_ + k0 + p_ * 8;
            float4 a0 = *(const float4*)(src);
            float4 a1 = *(const float4*)(src + 4);
            As[p_ * 8 + 0][r_] = a0.x; As[p_ * 8 + 1][r_] = a0.y;
            As[p_ * 8 + 2][r_] = a0.z; As[p_ * 8 + 3][r_] = a0.w;
            As[p_ * 8 + 4][r_] = a1.x; As[p_ * 8 + 5][r_] = a1.y;
            As[p_ * 8 + 6][r_] = a1.z; As[p_ * 8 + 7][r_] = a1.w;
        }
        *(float4*)(&Bs[vr][vd]) =
            *(const float4*)(vb + (size_t)(k0 + vr) * DKV + vd);
        __syncthreads();
#pragma unroll
        for (int k = 0; k < 16; k++) {
            float a[8], b[4];
            *(float4*)(a)     = *(float4*)(&As[k][ty * 4]);
            *(float4*)(a + 4) = *(float4*)(&As[k][64 + ty * 4]);
            *(float4*)(b)     = *(float4*)(&Bs[k][tx * 4]);
#pragma unroll
            for (int ii = 0; ii < 8; ii++)
#pragma unroll
                for (int jj = 0; jj < 4; jj++) acc[ii][jj] += a[ii] * b[jj];
        }
    }

    const int b_ = bh >> 4, h_ = bh & 15;
#pragma unroll
    for (int ii = 0; ii < 8; ii++) {
        int i = i0 + ((ii < 4) ? (ty * 4 + ii) : (64 + ty * 4 + ii - 4));
        float4 o;
        o.x = acc[ii][0]; o.y = acc[ii][1]; o.z = acc[ii][2]; o.w = acc[ii][3];
        *(float4*)(g_ctx + ((size_t)(b_ * SS_ + i)) * DM + h_ * DKV + tx * 4) = o;
    }
}

// ===========================================================================
// Kernel 6: edge-value context:  for fixed i:
//   ctx[bh @ i, d] += sum_j W[bh,i,j] * EV[i,j,d]
// Block = i; output tile [128 bh x 64 d], K=512 in chunks of 16.
// ===========================================================================
__global__ __launch_bounds__(256) void k_ctx_edge(const float* __restrict__ EV)
{
    const int i = blockIdx.x;
    const int tid = threadIdx.x;
    const int tx = tid & 15, ty = tid >> 4;
    const int r_ = tid >> 1, p_ = tid & 1;
    const int vr = tid >> 4, vd = (tid & 15) * 4;

    __shared__ float As[16][132];   // [j][bh]
    __shared__ float Bs[16][68];    // [j][d]

    float acc[8][4];
#pragma unroll
    for (int a = 0; a < 8; a++)
#pragma unroll
        for (int b = 0; b < 4; b++) acc[a][b] = 0.f;

    for (int k0 = 0; k0 < SS_; k0 += 16) {
        __syncthreads();
        {
            const float* src = g_sc + ((size_t)r_ * SS_ + i) * SS_ + k0 + p_ * 8;
            float4 a0 = *(const float4*)(src);
            float4 a1 = *(const float4*)(src + 4);
            As[p_ * 8 + 0][r_] = a0.x; As[p_ * 8 + 1][r_] = a0.y;
            As[p_ * 8 + 2][r_] = a0.z; As[p_ * 8 + 3][r_] = a0.w;
            As[p_ * 8 + 4][r_] = a1.x; As[p_ * 8 + 5][r_] = a1.y;
            As[p_ * 8 + 6][r_] = a1.z; As[p_ * 8 + 7][r_] = a1.w;
        }
        *(float4*)(&Bs[vr][vd]) =
            *(const float4*)(EV + ((size_t)i * SS_ + k0 + vr) * DKV + vd);
        __syncthreads();
#pragma unroll
        for (int k = 0; k < 16; k++) {
            float a[8], b[4];
            *(float4*)(a)     = *(float4*)(&As[k][ty * 4]);
            *(float4*)(a + 4) = *(float4*)(&As[k][64 + ty * 4]);
            *(float4*)(b)     = *(float4*)(&Bs[k][tx * 4]);
#pragma unroll
            for (int ii = 0; ii < 8; ii++)
#pragma unroll
                for (int jj = 0; jj < 4; jj++) acc[ii][jj] += a[ii] * b[jj];
        }
    }

#pragma unroll
    for (int ii = 0; ii < 8; ii++) {
        int bh = (ii < 4) ? (ty * 4 + ii) : (64 + ty * 4 + ii - 4);
        int b_ = bh >> 4, h_ = bh & 15;
        float* dst = g_ctx + ((size_t)(b_ * SS_ + i)) * DM + h_ * DKV + tx * 4;
        float4 prev = *(const float4*)(dst);
        prev.x += acc[ii][0]; prev.y += acc[ii][1];
        prev.z += acc[ii][2]; prev.w += acc[ii][3];
        *(float4*)(dst) = prev;
    }
}

// ===========================================================================
// Kernel 7: output projection:  out[4096,1024] = ctx @ Wo + bo
// Same structure as k_proj, plain row-major epilogue.
// ===========================================================================
__global__ __launch_bounds__(256) void k_out(
    const float* __restrict__ Wo, const float* __restrict__ bo,
    float* __restrict__ out)
{
    __shared__ float As[8][132];
    __shared__ float Bs[8][132];

    const int tid = threadIdx.x;
    const int m0 = blockIdx.x * 128;
    const int n0 = blockIdx.y * 128;

    const int ar = tid >> 1, ac = (tid & 1) * 4;
    const int br = tid >> 5, bc = (tid & 31) * 4;
    const int tx = tid & 15, ty = tid >> 4;

    float acc[8][8];
#pragma unroll
    for (int i = 0; i < 8; i++)
#pragma unroll
        for (int j = 0; j < 8; j++) acc[i][j] = 0.f;

    for (int k0 = 0; k0 < DM; k0 += 8) {
        float4 av = *(const float4*)(g_ctx + (size_t)(m0 + ar) * DM + k0 + ac);
        As[ac + 0][ar] = av.x; As[ac + 1][ar] = av.y;
        As[ac + 2][ar] = av.z; As[ac + 3][ar] = av.w;
        *(float4*)(&Bs[br][bc]) =
            *(const float4*)(Wo + (size_t)(k0 + br) * DM + n0 + bc);
        __syncthreads();
#pragma unroll
        for (int k = 0; k < 8; k++) {
            float a[8], b[8];
            *(float4*)(a)     = *(float4*)(&As[k][ty * 4]);
            *(float4*)(a + 4) = *(float4*)(&As[k][64 + ty * 4]);
            *(float4*)(b)     = *(float4*)(&Bs[k][tx * 4]);
            *(float4*)(b + 4) = *(float4*)(&Bs[k][64 + tx * 4]);
#pragma unroll
            for (int i = 0; i < 8; i++)
#pragma unroll
                for (int j = 0; j < 8; j++) acc[i][j] += a[i] * b[j];
        }
        __syncthreads();
    }

#pragma unroll
    for (int i = 0; i < 8; i++) {
        int row = m0 + ((i < 4) ? (ty * 4 + i) : (64 + ty * 4 + i - 4));
#pragma unroll
        for (int jh = 0; jh < 2; jh++) {
            int col = n0 + jh * 64 + tx * 4;
            float4 o;
            o.x = acc[i][jh * 4 + 0] + bo[col + 0];
            o.y = acc[i][jh * 4 + 1] + bo[col + 1];
            o.z = acc[i][jh * 4 + 2] + bo[col + 2];
            o.w = acc[i][jh * 4 + 3] + bo[col + 3];
            *(float4*)(out + (size_t)row * DM + col) = o;
        }
    }
}

// ===========================================================================
// Launcher
// ===========================================================================
extern "C" void kernel_launch(void* const* d_in, const int* in_sizes, int n_in,
                              void* d_out, int out_size)
{
    const float* queries     = (const float*)d_in[0];
    const float* edges_key   = (const float*)d_in[1];
    const float* edges_value = (const float*)d_in[2];
    const float* attn_bias   = (const float*)d_in[3];
    const float* Wq = (const float*)d_in[4];
    const float* bq = (const float*)d_in[5];
    const float* Wk = (const float*)d_in[6];
    const float* bk = (const float*)d_in[7];
    const float* Wv = (const float*)d_in[8];
    const float* bv = (const float*)d_in[9];
    const float* Wo = (const float*)d_in[10];
    const float* bo = (const float*)d_in[11];
    float* out = (float*)d_out;

    // Launch on whichever stream is actually being captured (hedge: if the
    // harness captures the per-thread default stream while this TU was
    // compiled with legacy default, route explicitly).
    cudaStream_t st = 0;
    cudaStreamCaptureStatus cs = cudaStreamCaptureStatusNone;
    if (cudaStreamIsCapturing(cudaStreamPerThread, &cs) == cudaSuccess &&
        cs == cudaStreamCaptureStatusActive)
        st = cudaStreamPerThread;

    k_proj<<<dim3(32, 8, 3), 256, 0, st>>>(queries, Wq, bq, Wk, bk, Wv, bv);
    k_edge_scores<<<dim3(4, 512), 256, 0, st>>>(edges_key);
    k_content_scores<<<dim3(4, 4, 128), 256, 0, st>>>(attn_bias);
    k_softmax<<<dim3(8192), 256, 0, st>>>();
    k_ctx_content<<<dim3(4, 128), 256, 0, st>>>();
    k_ctx_edge<<<dim3(512), 256, 0, st>>>(edges_value);
    k_out<<<dim3(32, 8), 256, 0, st>>>(Wo, bo, out);
}

// round 3
// speedup vs baseline: 1.3539x; 1.3539x over previous
#include <cuda_runtime.h>
#include <cuda_bf16.h>
#include <cstdint>

// ---------------------------------------------------------------------------
// Problem constants: B=8, S=512, D_MODEL=1024, H=16, DK=DV=64, BH=128
// ---------------------------------------------------------------------------
#define BB   8
#define SS_  512
#define DM   1024
#define HH   16
#define DKV  64
#define BH   128
#define SCALE 0.125f

// ---------------------------------------------------------------------------
// Scratch (device globals)
// ---------------------------------------------------------------------------
__device__ float g_q[(size_t)BH * SS_ * DKV];
__device__ float g_k[(size_t)BH * SS_ * DKV];
__device__ float g_v[(size_t)BH * SS_ * DKV];
__device__ float g_sc[(size_t)BH * SS_ * SS_];
__device__ float g_ctx[(size_t)BB * SS_ * DM];

// bf16-split staging, plain row-major [row][3072]
// A' = [Xh | Xh | Xl]   (4096 rows)
// B' = [Wh | Wl | Wh]   (rows = output col n)
__device__ __align__(16) __nv_bfloat16 g_A   [(size_t)4096 * 3072];
__device__ __align__(16) __nv_bfloat16 g_Actx[(size_t)4096 * 3072];
__device__ __align__(16) __nv_bfloat16 g_Bqkv[(size_t)3072 * 3072];
__device__ __align__(16) __nv_bfloat16 g_Bo  [(size_t)1024 * 3072];

__device__ __forceinline__ uint32_t s2u(const void* p) {
    uint32_t a;
    asm("{ .reg .u64 t; cvta.to.shared.u64 t, %1; cvt.u32.u64 %0, t; }"
        : "=r"(a) : "l"(p));
    return a;
}
__device__ __forceinline__ uint32_t pk2(__nv_bfloat16 a, __nv_bfloat16 b) {
    return (uint32_t)__bfloat16_as_ushort(a) | ((uint32_t)__bfloat16_as_ushort(b) << 16);
}

#define CP_ASYNC16(dst, src) \
    asm volatile("cp.async.cg.shared.global [%0], [%1], 16;" :: "r"(dst), "l"(src) : "memory")
#define CP_COMMIT() asm volatile("cp.async.commit_group;" ::: "memory")
#define CP_WAIT0()  asm volatile("cp.async.wait_group 0;" ::: "memory")

#define LDMATX4(r0, r1, r2, r3, addr) \
    asm volatile("ldmatrix.sync.aligned.m8n8.x4.shared.b16 {%0,%1,%2,%3}, [%4];" \
        : "=r"(r0), "=r"(r1), "=r"(r2), "=r"(r3) : "r"(addr))

#define MMA16816(c, a, b) \
    asm volatile("mma.sync.aligned.m16n8k16.row.col.f32.bf16.bf16.f32 " \
        "{%0,%1,%2,%3}, {%4,%5,%6,%7}, {%8,%9}, {%0,%1,%2,%3};" \
        : "+f"((c)[0]), "+f"((c)[1]), "+f"((c)[2]), "+f"((c)[3]) \
        : "r"((a)[0]), "r"((a)[1]), "r"((a)[2]), "r"((a)[3]), \
          "r"((b)[0]), "r"((b)[1]))

// ===========================================================================
// Split conversion: fp32 [4096,1024] -> bf16 split [4096,3072]
// which=0: src=queries -> g_A ; which=1: src=g_ctx -> g_Actx
// ===========================================================================
__global__ __launch_bounds__(256) void k_split(const float* __restrict__ src_in, int which)
{
    const float* src = which ? (const float*)g_ctx : src_in;
    __nv_bfloat16* dst = which ? g_Actx : g_A;
    int idx = blockIdx.x * 256 + threadIdx.x;
    int r = idx >> 7;
    int c0 = (idx & 127) << 3;
    const float* s = src + (size_t)r * 1024 + c0;
    float4 v0 = *(const float4*)(s);
    float4 v1 = *(const float4*)(s + 4);
    float f[8] = {v0.x, v0.y, v0.z, v0.w, v1.x, v1.y, v1.z, v1.w};
    uint4 H, L;
    uint32_t hu[4], lu[4];
#pragma unroll
    for (int i = 0; i < 4; i++) {
        __nv_bfloat16 h0 = __float2bfloat16(f[2*i]);
        __nv_bfloat16 h1 = __float2bfloat16(f[2*i+1]);
        __nv_bfloat16 l0 = __float2bfloat16(f[2*i]   - __bfloat162float(h0));
        __nv_bfloat16 l1 = __float2bfloat16(f[2*i+1] - __bfloat162float(h1));
        hu[i] = pk2(h0, h1); lu[i] = pk2(l0, l1);
    }
    H.x = hu[0]; H.y = hu[1]; H.z = hu[2]; H.w = hu[3];
    L.x = lu[0]; L.y = lu[1]; L.z = lu[2]; L.w = lu[3];
    __nv_bfloat16* row = dst + (size_t)r * 3072;
    *(uint4*)(row + c0)        = H;   // block 0: Xh
    *(uint4*)(row + 1024 + c0) = H;   // block 1: Xh
    *(uint4*)(row + 2048 + c0) = L;   // block 2: Xl
}

// ===========================================================================
// Weight split+transpose: W[1024(k),1024(n)] -> B'[n][3072]
// row n: [0,1024)=Wh, [1024,2048)=Wl, [2048,3072)=Wh
// slot 0/1/2 -> g_Bqkv + slot*1024*3072 ; slot 3 -> g_Bo
// ===========================================================================
__global__ __launch_bounds__(256) void k_wsplit(const float* __restrict__ W, int slot)
{
    __nv_bfloat16* dst = (slot < 3) ? (g_Bqkv + (size_t)slot * 1024 * 3072) : g_Bo;
    int nl = blockIdx.x * 256 + threadIdx.x;
    int k0 = blockIdx.y << 3;
    uint4 H, L;
    uint32_t hu[4], lu[4];
#pragma unroll
    for (int i = 0; i < 4; i++) {
        float f0 = W[(size_t)(k0 + 2*i)     * 1024 + nl];
        float f1 = W[(size_t)(k0 + 2*i + 1) * 1024 + nl];
        __nv_bfloat16 h0 = __float2bfloat16(f0);
        __nv_bfloat16 h1 = __float2bfloat16(f1);
        __nv_bfloat16 l0 = __float2bfloat16(f0 - __bfloat162float(h0));
        __nv_bfloat16 l1 = __float2bfloat16(f1 - __bfloat162float(h1));
        hu[i] = pk2(h0, h1); lu[i] = pk2(l0, l1);
    }
    H.x = hu[0]; H.y = hu[1]; H.z = hu[2]; H.w = hu[3];
    L.x = lu[0]; L.y = lu[1]; L.z = lu[2]; L.w = lu[3];
    __nv_bfloat16* row = dst + (size_t)nl * 3072;
    *(uint4*)(row + k0)        = H;   // Wh
    *(uint4*)(row + 1024 + k0) = L;   // Wl
    *(uint4*)(row + 2048 + k0) = H;   // Wh
}

// ===========================================================================
// bf16 mma.sync GEMM: C[4096, N] = A'[4096,3072] @ B'[N,3072]^T
// 128x128 CTA tile, 8 warps (2x4) of 64x32 warp tiles, BK=32,
// cp.async double buffer, padded SMEM rows (40 bf16 = 80B) for ldmatrix.
// mode 0: QKV (N=3072) -> g_q/g_k/g_v (+biases)   mode 1: OUT -> outp (+bo)
// ===========================================================================
#define KTOT   3072
#define NCHUNK 96           // KTOT / 32
#define LDS_   40           // padded row stride in bf16 elements (80 bytes)
#define TILEB  (128 * LDS_ * 2)   // bytes per matrix per buffer (10240)

__global__ __launch_bounds__(256) void k_gemm_bf16(
    const float* __restrict__ b0p, const float* __restrict__ b1p,
    const float* __restrict__ b2p, float* __restrict__ outp, int mode)
{
    __shared__ __align__(16) char smem[2 * 2 * TILEB];  // [buf][A|B]

    const int tid  = threadIdx.x;
    const int wid  = tid >> 5, lane = tid & 31;
    const int wm   = wid >> 2, wn = wid & 3;          // warp grid 2x4
    const int m0   = blockIdx.y * 128, n0 = blockIdx.x * 128;
    const uint32_t sbase = s2u(smem);

    const __nv_bfloat16* __restrict__ Ag = mode ? g_Actx : g_A;
    const __nv_bfloat16* __restrict__ Bg = mode ? g_Bo   : g_Bqkv;

    // global load coords: 2 x 16B per thread per matrix per chunk
    const int lrow0 = tid >> 2;            // rows 0..63   (u=0)
    const int lseg  = (tid & 3) << 3;      // k element offset 0/8/16/24

    float acc[4][4][4];
#pragma unroll
    for (int i = 0; i < 4; i++)
#pragma unroll
        for (int j = 0; j < 4; j++)
#pragma unroll
            for (int q = 0; q < 4; q++) acc[i][j][q] = 0.f;

    // prologue: chunk 0 -> buffer 0
    {
        uint32_t dA = sbase, dB = sbase + TILEB;
#pragma unroll
        for (int u = 0; u < 2; u++) {
            int row = lrow0 + u * 64;
            CP_ASYNC16(dA + (row * LDS_ + lseg) * 2,
                       Ag + (size_t)(m0 + row) * KTOT + lseg);
            CP_ASYNC16(dB + (row * LDS_ + lseg) * 2,
                       Bg + (size_t)(n0 + row) * KTOT + lseg);
        }
        CP_COMMIT();
    }

    for (int c = 0; c < NCHUNK; c++) {
        CP_WAIT0();
        __syncthreads();

        if (c + 1 < NCHUNK) {
            uint32_t dA = sbase + ((c + 1) & 1) * 2 * TILEB;
            uint32_t dB = dA + TILEB;
            const int koff = (c + 1) * 32 + lseg;
#pragma unroll
            for (int u = 0; u < 2; u++) {
                int row = lrow0 + u * 64;
                CP_ASYNC16(dA + (row * LDS_ + lseg) * 2,
                           Ag + (size_t)(m0 + row) * KTOT + koff);
                CP_ASYNC16(dB + (row * LDS_ + lseg) * 2,
                           Bg + (size_t)(n0 + row) * KTOT + koff);
            }
            CP_COMMIT();
        }

        const uint32_t bufA = sbase + (c & 1) * 2 * TILEB;
        const uint32_t bufB = bufA + TILEB;
        const int lr = lane & 15, lc = (lane >> 4) << 3;

#pragma unroll
        for (int ks = 0; ks < 2; ks++) {
            uint32_t a[4][4];
#pragma unroll
            for (int mi = 0; mi < 4; mi++) {
                uint32_t addr = bufA +
                    ((wm * 64 + mi * 16 + lr) * LDS_ + ks * 16 + lc) * 2;
                LDMATX4(a[mi][0], a[mi][1], a[mi][2], a[mi][3], addr);
            }
            uint32_t b[4][2];
#pragma unroll
            for (int ni2 = 0; ni2 < 2; ni2++) {
                uint32_t r0, r1, r2, r3;
                uint32_t addr = bufB +
                    ((wn * 32 + ni2 * 16 + lr) * LDS_ + ks * 16 + lc) * 2;
                LDMATX4(r0, r1, r2, r3, addr);
                b[2 * ni2][0] = r0;     b[2 * ni2][1] = r2;
                b[2 * ni2 + 1][0] = r1; b[2 * ni2 + 1][1] = r3;
            }
#pragma unroll
            for (int mi = 0; mi < 4; mi++)
#pragma unroll
                for (int ni = 0; ni < 4; ni++)
                    MMA16816(acc[mi][ni], a[mi], b[ni]);
        }
        __syncthreads();
    }

    // -------- epilogue --------
    const int g  = lane >> 2;        // row group 0..7
    const int tc = (lane & 3) << 1;  // col pair 0/2/4/6

    if (mode == 0) {
        const int proj = n0 >> 10;
        const float* bias = (proj == 0) ? b0p : (proj == 1) ? b1p : b2p;
        float* base = (proj == 0) ? g_q : (proj == 1) ? g_k : g_v;
        const int nl0 = (n0 & 1023) + wn * 32;
#pragma unroll
        for (int mi = 0; mi < 4; mi++) {
            int m = m0 + wm * 64 + mi * 16 + g;
            int b_ = m >> 9, s_ = m & 511;
#pragma unroll
            for (int ni = 0; ni < 4; ni++) {
                int ncol = nl0 + ni * 8 + tc;
                int h = ncol >> 6, d = ncol & 63;
                float* p0 = base + ((size_t)((b_ * HH + h) * SS_ + s_)) * DKV + d;
                float2 o0 = {acc[mi][ni][0] + bias[ncol],
                             acc[mi][ni][1] + bias[ncol + 1]};
                *(float2*)p0 = o0;
                int m2 = m + 8, s2 = m2 & 511, b2 = m2 >> 9;
                float* p1 = base + ((size_t)((b2 * HH + h) * SS_ + s2)) * DKV + d;
                float2 o1 = {acc[mi][ni][2] + bias[ncol],
                             acc[mi][ni][3] + bias[ncol + 1]};
                *(float2*)p1 = o1;
            }
        }
    } else {
#pragma unroll
        for (int mi = 0; mi < 4; mi++) {
            int m = m0 + wm * 64 + mi * 16 + g;
#pragma unroll
            for (int ni = 0; ni < 4; ni++) {
                int ncol = n0 + wn * 32 + ni * 8 + tc;
                float2 o0 = {acc[mi][ni][0] + b0p[ncol],
                             acc[mi][ni][1] + b0p[ncol + 1]};
                float2 o1 = {acc[mi][ni][2] + b0p[ncol],
                             acc[mi][ni][3] + b0p[ncol + 1]};
                *(float2*)(outp + (size_t)m * DM + ncol) = o0;
                *(float2*)(outp + (size_t)(m + 8) * DM + ncol) = o1;
            }
        }
    }
}

// ===========================================================================
// Kernel: edge-key scores (fp32)
// ===========================================================================
__global__ __launch_bounds__(256) void k_edge_scores(const float* __restrict__ EK)
{
    const int i  = blockIdx.y;
    const int j0 = blockIdx.x * 128;
    const int tid = threadIdx.x;
    const int tx = tid & 15, ty = tid >> 4;

    __shared__ float Qs[128][68];
    __shared__ float Es[16][132];

    {
        int d4 = (tid & 15) * 4;
#pragma unroll
        for (int r = 0; r < 8; r++) {
            int bh = r * 16 + (tid >> 4);
            *(float4*)(&Qs[bh][d4]) =
                *(const float4*)(g_q + ((size_t)bh * SS_ + i) * DKV + d4);
        }
    }

    float acc[8][8];
#pragma unroll
    for (int a = 0; a < 8; a++)
#pragma unroll
        for (int b = 0; b < 8; b++) acc[a][b] = 0.f;

    const int er = tid >> 1, ep = tid & 1;

    for (int dk0 = 0; dk0 < 64; dk0 += 16) {
        __syncthreads();
        const float* Erow = EK + ((size_t)i * SS_ + j0 + er) * DKV + dk0 + ep * 8;
        float4 e0 = *(const float4*)(Erow);
        float4 e1 = *(const float4*)(Erow + 4);
        Es[ep * 8 + 0][er] = e0.x; Es[ep * 8 + 1][er] = e0.y;
        Es[ep * 8 + 2][er] = e0.z; Es[ep * 8 + 3][er] = e0.w;
        Es[ep * 8 + 4][er] = e1.x; Es[ep * 8 + 5][er] = e1.y;
        Es[ep * 8 + 6][er] = e1.z; Es[ep * 8 + 7][er] = e1.w;
        __syncthreads();
#pragma unroll
        for (int k = 0; k < 16; k++) {
            float b[8];
            *(float4*)(b)     = *(float4*)(&Es[k][tx * 4]);
            *(float4*)(b + 4) = *(float4*)(&Es[k][64 + tx * 4]);
            float a[8];
#pragma unroll
            for (int ii = 0; ii < 8; ii++) {
                int bh = (ii < 4) ? (ty * 4 + ii) : (64 + ty * 4 + ii - 4);
                a[ii] = Qs[bh][dk0 + k];
            }
#pragma unroll
            for (int ii = 0; ii < 8; ii++)
#pragma unroll
                for (int jj = 0; jj < 8; jj++) acc[ii][jj] += a[ii] * b[jj];
        }
    }

#pragma unroll
    for (int ii = 0; ii < 8; ii++) {
        int bh = (ii < 4) ? (ty * 4 + ii) : (64 + ty * 4 + ii - 4);
        float* dst = g_sc + ((size_t)bh * SS_ + i) * SS_ + j0;
#pragma unroll
        for (int jh = 0; jh < 2; jh++) {
            float4 o;
            o.x = acc[ii][jh * 4 + 0] * SCALE;
            o.y = acc[ii][jh * 4 + 1] * SCALE;
            o.z = acc[ii][jh * 4 + 2] * SCALE;
            o.w = acc[ii][jh * 4 + 3] * SCALE;
            *(float4*)(dst + jh * 64 + tx * 4) = o;
        }
    }
}

// ===========================================================================
// Kernel: content scores (fp32)
// ===========================================================================
__global__ __launch_bounds__(256) void k_content_scores(const float* __restrict__ bias)
{
    const int bh = blockIdx.z;
    const int i0 = blockIdx.y * 128;
    const int j0 = blockIdx.x * 128;
    const int tid = threadIdx.x;
    const int tx = tid & 15, ty = tid >> 4;
    const int r_ = tid >> 1, p_ = tid & 1;

    __shared__ float As[16][132];
    __shared__ float Bs[16][132];

    const float* qb = g_q + (size_t)bh * SS_ * DKV;
    const float* kb = g_k + (size_t)bh * SS_ * DKV;

    float acc[8][8];
#pragma unroll
    for (int a = 0; a < 8; a++)
#pragma unroll
        for (int b = 0; b < 8; b++) acc[a][b] = 0.f;

    for (int dk0 = 0; dk0 < 64; dk0 += 16) {
        __syncthreads();
        {
            const float* src = qb + (size_t)(i0 + r_) * DKV + dk0 + p_ * 8;
            float4 a0 = *(const float4*)(src);
            float4 a1 = *(const float4*)(src + 4);
            As[p_ * 8 + 0][r_] = a0.x; As[p_ * 8 + 1][r_] = a0.y;
            As[p_ * 8 + 2][r_] = a0.z; As[p_ * 8 + 3][r_] = a0.w;
            As[p_ * 8 + 4][r_] = a1.x; As[p_ * 8 + 5][r_] = a1.y;
            As[p_ * 8 + 6][r_] = a1.z; As[p_ * 8 + 7][r_] = a1.w;
        }
        {
            const float* src = kb + (size_t)(j0 + r_) * DKV + dk0 + p_ * 8;
            float4 b0 = *(const float4*)(src);
            float4 b1 = *(const float4*)(src + 4);
            Bs[p_ * 8 + 0][r_] = b0.x; Bs[p_ * 8 + 1][r_] = b0.y;
            Bs[p_ * 8 + 2][r_] = b0.z; Bs[p_ * 8 + 3][r_] = b0.w;
            Bs[p_ * 8 + 4][r_] = b1.x; Bs[p_ * 8 + 5][r_] = b1.y;
            Bs[p_ * 8 + 6][r_] = b1.z; Bs[p_ * 8 + 7][r_] = b1.w;
        }
        __syncthreads();
#pragma unroll
        for (int k = 0; k < 16; k++) {
            float a[8], b[8];
            *(float4*)(a)     = *(float4*)(&As[k][ty * 4]);
            *(float4*)(a + 4) = *(float4*)(&As[k][64 + ty * 4]);
            *(float4*)(b)     = *(float4*)(&Bs[k][tx * 4]);
            *(float4*)(b + 4) = *(float4*)(&Bs[k][64 + tx * 4]);
#pragma unroll
            for (int ii = 0; ii < 8; ii++)
#pragma unroll
                for (int jj = 0; jj < 8; jj++) acc[ii][jj] += a[ii] * b[jj];
        }
    }

#pragma unroll
    for (int ii = 0; ii < 8; ii++) {
        int row = i0 + ((ii < 4) ? (ty * 4 + ii) : (64 + ty * 4 + ii - 4));
        size_t base = ((size_t)bh * SS_ + row) * SS_ + j0;
#pragma unroll
        for (int jh = 0; jh < 2; jh++) {
            int c = jh * 64 + tx * 4;
            float4 prev = *(const float4*)(g_sc + base + c);
            float4 bz   = *(const float4*)(bias + base + c);
            float4 o;
            o.x = acc[ii][jh * 4 + 0] * SCALE + prev.x + bz.x;
            o.y = acc[ii][jh * 4 + 1] * SCALE + prev.y + bz.y;
            o.z = acc[ii][jh * 4 + 2] * SCALE + prev.z + bz.z;
            o.w = acc[ii][jh * 4 + 3] * SCALE + prev.w + bz.w;
            *(float4*)(g_sc + base + c) = o;
        }
    }
}

// ===========================================================================
// Kernel: softmax
// ===========================================================================
__global__ __launch_bounds__(256) void k_softmax()
{
    const int warp = threadIdx.x >> 5, lane = threadIdx.x & 31;
    const size_t row = (size_t)blockIdx.x * 8 + warp;
    float* p = g_sc + row * SS_;

    float4 v[4];
    float mx = -1e30f;
#pragma unroll
    for (int w = 0; w < 4; w++) {
        v[w] = *(const float4*)(p + w * 128 + lane * 4);
        mx = fmaxf(mx, fmaxf(fmaxf(v[w].x, v[w].y), fmaxf(v[w].z, v[w].w)));
    }
#pragma unroll
    for (int o = 16; o > 0; o >>= 1) mx = fmaxf(mx, __shfl_xor_sync(~0u, mx, o));

    float sum = 0.f;
#pragma unroll
    for (int w = 0; w < 4; w++) {
        v[w].x = __expf(v[w].x - mx); v[w].y = __expf(v[w].y - mx);
        v[w].z = __expf(v[w].z - mx); v[w].w = __expf(v[w].w - mx);
        sum += v[w].x + v[w].y + v[w].z + v[w].w;
    }
#pragma unroll
    for (int o = 16; o > 0; o >>= 1) sum += __shfl_xor_sync(~0u, sum, o);
    float r = 1.f / sum;
#pragma unroll
    for (int w = 0; w < 4; w++) {
        v[w].x *= r; v[w].y *= r; v[w].z *= r; v[w].w *= r;
        *(float4*)(p + w * 128 + lane * 4) = v[w];
    }
}

// ===========================================================================
// Kernel: content context (fp32)
// ===========================================================================
__global__ __launch_bounds__(256) void k_ctx_content()
{
    const int bh = blockIdx.y;
    const int i0 = blockIdx.x * 128;
    const int tid = threadIdx.x;
    const int tx = tid & 15, ty = tid >> 4;
    const int r_ = tid >> 1, p_ = tid & 1;
    const int vr = tid >> 4, vd = (tid & 15) * 4;

    __shared__ float As[16][132];
    __shared__ float Bs[16][68];

    const float* wb = g_sc + ((size_t)bh * SS_ + i0) * SS_;
    const float* vb = g_v + (size_t)bh * SS_ * DKV;

    float acc[8][4];
#pragma unroll
    for (int a = 0; a < 8; a++)
#pragma unroll
        for (int b = 0; b < 4; b++) acc[a][b] = 0.f;

    for (int k0 = 0; k0 < SS_; k0 += 16) {
        __syncthreads();
        {
            const float* src = wb + (size_t)r_ * SS_ + k0 + p_ * 8;
            float4 a0 = *(const float4*)(src);
            float4 a1 = *(const float4*)(src + 4);
            As[p_ * 8 + 0][r_] = a0.x; As[p_ * 8 + 1][r_] = a0.y;
            As[p_ * 8 + 2][r_] = a0.z; As[p_ * 8 + 3][r_] = a0.w;
            As[p_ * 8 + 4][r_] = a1.x; As[p_ * 8 + 5][r_] = a1.y;
            As[p_ * 8 + 6][r_] = a1.z; As[p_ * 8 + 7][r_] = a1.w;
        }
        *(float4*)(&Bs[vr][vd]) =
            *(const float4*)(vb + (size_t)(k0 + vr) * DKV + vd);
        __syncthreads();
#pragma unroll
        for (int k = 0; k < 16; k++) {
            float a[8], b[4];
            *(float4*)(a)     = *(float4*)(&As[k][ty * 4]);
            *(float4*)(a + 4) = *(float4*)(&As[k][64 + ty * 4]);
            *(float4*)(b)     = *(float4*)(&Bs[k][tx * 4]);
#pragma unroll
            for (int ii = 0; ii < 8; ii++)
#pragma unroll
                for (int jj = 0; jj < 4; jj++) acc[ii][jj] += a[ii] * b[jj];
        }
    }

    const int b_ = bh >> 4, h_ = bh & 15;
#pragma unroll
    for (int ii = 0; ii < 8; ii++) {
        int i = i0 + ((ii < 4) ? (ty * 4 + ii) : (64 + ty * 4 + ii - 4));
        float4 o;
        o.x = acc[ii][0]; o.y = acc[ii][1]; o.z = acc[ii][2]; o.w = acc[ii][3];
        *(float4*)(g_ctx + ((size_t)(b_ * SS_ + i)) * DM + h_ * DKV + tx * 4) = o;
    }
}

// ===========================================================================
// Kernel: edge-value context (fp32)
// ===========================================================================
__global__ __launch_bounds__(256) void k_ctx_edge(const float* __restrict__ EV)
{
    const int i = blockIdx.x;
    const int tid = threadIdx.x;
    const int tx = tid & 15, ty = tid >> 4;
    const int r_ = tid >> 1, p_ = tid & 1;
    const int vr = tid >> 4, vd = (tid & 15) * 4;

    __shared__ float As[16][132];
    __shared__ float Bs[16][68];

    float acc[8][4];
#pragma unroll
    for (int a = 0; a < 8; a++)
#pragma unroll
        for (int b = 0; b < 4; b++) acc[a][b] = 0.f;

    for (int k0 = 0; k0 < SS_; k0 += 16) {
        __syncthreads();
        {
            const float* src = g_sc + ((size_t)r_ * SS_ + i) * SS_ + k0 + p_ * 8;
            float4 a0 = *(const float4*)(src);
            float4 a1 = *(const float4*)(src + 4);
            As[p_ * 8 + 0][r_] = a0.x; As[p_ * 8 + 1][r_] = a0.y;
            As[p_ * 8 + 2][r_] = a0.z; As[p_ * 8 + 3][r_] = a0.w;
            As[p_ * 8 + 4][r_] = a1.x; As[p_ * 8 + 5][r_] = a1.y;
            As[p_ * 8 + 6][r_] = a1.z; As[p_ * 8 + 7][r_] = a1.w;
        }
        *(float4*)(&Bs[vr][vd]) =
            *(const float4*)(EV + ((size_t)i * SS_ + k0 + vr) * DKV + vd);
        __syncthreads();
#pragma unroll
        for (int k = 0; k < 16; k++) {
            float a[8], b[4];
            *(float4*)(a)     = *(float4*)(&As[k][ty * 4]);
            *(float4*)(a + 4) = *(float4*)(&As[k][64 + ty * 4]);
            *(float4*)(b)     = *(float4*)(&Bs[k][tx * 4]);
#pragma unroll
            for (int ii = 0; ii < 8; ii++)
#pragma unroll
                for (int jj = 0; jj < 4; jj++) acc[ii][jj] += a[ii] * b[jj];
        }
    }

#pragma unroll
    for (int ii = 0; ii < 8; ii++) {
        int bh = (ii < 4) ? (ty * 4 + ii) : (64 + ty * 4 + ii - 4);
        int b_ = bh >> 4, h_ = bh & 15;
        float* dst = g_ctx + ((size_t)(b_ * SS_ + i)) * DM + h_ * DKV + tx * 4;
        float4 prev = *(const float4*)(dst);
        prev.x += acc[ii][0]; prev.y += acc[ii][1];
        prev.z += acc[ii][2]; prev.w += acc[ii][3];
        *(float4*)(dst) = prev;
    }
}

// ===========================================================================
// Launcher
// ===========================================================================
extern "C" void kernel_launch(void* const* d_in, const int* in_sizes, int n_in,
                              void* d_out, int out_size)
{
    const float* queries     = (const float*)d_in[0];
    const float* edges_key   = (const float*)d_in[1];
    const float* edges_value = (const float*)d_in[2];
    const float* attn_bias   = (const float*)d_in[3];
    const float* Wq = (const float*)d_in[4];
    const float* bq = (const float*)d_in[5];
    const float* Wk = (const float*)d_in[6];
    const float* bk = (const float*)d_in[7];
    const float* Wv = (const float*)d_in[8];
    const float* bv = (const float*)d_in[9];
    const float* Wo = (const float*)d_in[10];
    const float* bo = (const float*)d_in[11];
    float* out = (float*)d_out;

    cudaStream_t st = 0;
    cudaStreamCaptureStatus cs = cudaStreamCaptureStatusNone;
    if (cudaStreamIsCapturing(cudaStreamPerThread, &cs) == cudaSuccess &&
        cs == cudaStreamCaptureStatusActive)
        st = cudaStreamPerThread;

    // split/convert inputs
    k_split <<<2048, 256, 0, st>>>(queries, 0);
    k_wsplit<<<dim3(4, 128), 256, 0, st>>>(Wq, 0);
    k_wsplit<<<dim3(4, 128), 256, 0, st>>>(Wk, 1);
    k_wsplit<<<dim3(4, 128), 256, 0, st>>>(Wv, 2);
    k_wsplit<<<dim3(4, 128), 256, 0, st>>>(Wo, 3);

    // QKV projection on tensor cores (mma.sync bf16, 3-term split)
    k_gemm_bf16<<<dim3(24, 32), 256, 0, st>>>(bq, bk, bv, nullptr, 0);

    // attention (fp32)
    k_edge_scores   <<<dim3(4, 512), 256, 0, st>>>(edges_key);
    k_content_scores<<<dim3(4, 4, 128), 256, 0, st>>>(attn_bias);
    k_softmax       <<<dim3(8192), 256, 0, st>>>();
    k_ctx_content   <<<dim3(4, 128), 256, 0, st>>>();
    k_ctx_edge      <<<dim3(512), 256, 0, st>>>(edges_value);

    // output projection on tensor cores
    k_split<<<2048, 256, 0, st>>>(nullptr, 1);
    k_gemm_bf16<<<dim3(8, 32), 256, 0, st>>>(bo, nullptr, nullptr, out, 1);
}

// round 4
// speedup vs baseline: 1.5087x; 1.1144x over previous
#include <cuda_runtime.h>
#include <cuda_bf16.h>
#include <cstdint>

// ---------------------------------------------------------------------------
// Problem constants: B=8, S=512, D_MODEL=1024, H=16, DK=DV=64, BH=128
// ---------------------------------------------------------------------------
#define BB   8
#define SS_  512
#define DM   1024
#define HH   16
#define DKV  64
#define BH   128
#define SCALE 0.125f

// ---------------------------------------------------------------------------
// Scratch (device globals)
// ---------------------------------------------------------------------------
__device__ float g_sc [(size_t)BH * SS_ * SS_];    // scores fp32 [bh,i,j]
__device__ float g_ctx[(size_t)BB * SS_ * DM];     // context fp32

// projection staging (3-term replicated layout)
__device__ __align__(16) __nv_bfloat16 g_A   [(size_t)4096 * 3072];
__device__ __align__(16) __nv_bfloat16 g_Actx[(size_t)4096 * 3072];
__device__ __align__(16) __nv_bfloat16 g_Bqkv[(size_t)3072 * 3072];
__device__ __align__(16) __nv_bfloat16 g_Bo  [(size_t)1024 * 3072];

// attention operand splits (hi/lo bf16)
__device__ __align__(16) __nv_bfloat16 qh [(size_t)BH * SS_ * DKV];
__device__ __align__(16) __nv_bfloat16 ql [(size_t)BH * SS_ * DKV];
__device__ __align__(16) __nv_bfloat16 kh [(size_t)BH * SS_ * DKV];
__device__ __align__(16) __nv_bfloat16 kl [(size_t)BH * SS_ * DKV];
__device__ __align__(16) __nv_bfloat16 vth[(size_t)BH * DKV * SS_];  // [bh,d,s]
__device__ __align__(16) __nv_bfloat16 vtl[(size_t)BH * DKV * SS_];
__device__ __align__(16) __nv_bfloat16 ekh [(size_t)SS_ * SS_ * DKV]; // [i,j,d]
__device__ __align__(16) __nv_bfloat16 ekl [(size_t)SS_ * SS_ * DKV];
__device__ __align__(16) __nv_bfloat16 evth[(size_t)SS_ * DKV * SS_]; // [i,d,j]
__device__ __align__(16) __nv_bfloat16 evtl[(size_t)SS_ * DKV * SS_];
__device__ __align__(16) __nv_bfloat16 wh [(size_t)BH * SS_ * SS_];   // [bh,i,j]
__device__ __align__(16) __nv_bfloat16 wl [(size_t)BH * SS_ * SS_];

__device__ __forceinline__ uint32_t s2u(const void* p) {
    uint32_t a;
    asm("{ .reg .u64 t; cvta.to.shared.u64 t, %1; cvt.u32.u64 %0, t; }"
        : "=r"(a) : "l"(p));
    return a;
}
__device__ __forceinline__ uint32_t pk2(__nv_bfloat16 a, __nv_bfloat16 b) {
    return (uint32_t)__bfloat16_as_ushort(a) | ((uint32_t)__bfloat16_as_ushort(b) << 16);
}

#define CP_ASYNC16(dst, src) \
    asm volatile("cp.async.cg.shared.global [%0], [%1], 16;" :: "r"(dst), "l"(src) : "memory")
#define CP_COMMIT() asm volatile("cp.async.commit_group;" ::: "memory")
#define CP_WAIT0()  asm volatile("cp.async.wait_group 0;" ::: "memory")

#define LDMATX4(r0, r1, r2, r3, addr) \
    asm volatile("ldmatrix.sync.aligned.m8n8.x4.shared.b16 {%0,%1,%2,%3}, [%4];" \
        : "=r"(r0), "=r"(r1), "=r"(r2), "=r"(r3) : "r"(addr))

#define MMA16816(c, a, b) \
    asm volatile("mma.sync.aligned.m16n8k16.row.col.f32.bf16.bf16.f32 " \
        "{%0,%1,%2,%3}, {%4,%5,%6,%7}, {%8,%9}, {%0,%1,%2,%3};" \
        : "+f"((c)[0]), "+f"((c)[1]), "+f"((c)[2]), "+f"((c)[3]) \
        : "r"((a)[0]), "r"((a)[1]), "r"((a)[2]), "r"((a)[3]), \
          "r"((b)[0]), "r"((b)[1]))

#define LDS_   40           // padded row stride in bf16 (80 bytes), conflict-free

// ===========================================================================
// Split conversion: fp32 [4096,1024] -> bf16 split [4096,3072]
// which=0: src=queries -> g_A ; which=1: src=g_ctx -> g_Actx
// ===========================================================================
__global__ __launch_bounds__(256) void k_split(const float* __restrict__ src_in, int which)
{
    const float* src = which ? (const float*)g_ctx : src_in;
    __nv_bfloat16* dst = which ? g_Actx : g_A;
    int idx = blockIdx.x * 256 + threadIdx.x;
    int r = idx >> 7;
    int c0 = (idx & 127) << 3;
    const float* s = src + (size_t)r * 1024 + c0;
    float4 v0 = *(const float4*)(s);
    float4 v1 = *(const float4*)(s + 4);
    float f[8] = {v0.x, v0.y, v0.z, v0.w, v1.x, v1.y, v1.z, v1.w};
    uint4 H, L;
    uint32_t hu[4], lu[4];
#pragma unroll
    for (int i = 0; i < 4; i++) {
        __nv_bfloat16 h0 = __float2bfloat16(f[2*i]);
        __nv_bfloat16 h1 = __float2bfloat16(f[2*i+1]);
        __nv_bfloat16 l0 = __float2bfloat16(f[2*i]   - __bfloat162float(h0));
        __nv_bfloat16 l1 = __float2bfloat16(f[2*i+1] - __bfloat162float(h1));
        hu[i] = pk2(h0, h1); lu[i] = pk2(l0, l1);
    }
    H.x = hu[0]; H.y = hu[1]; H.z = hu[2]; H.w = hu[3];
    L.x = lu[0]; L.y = lu[1]; L.z = lu[2]; L.w = lu[3];
    __nv_bfloat16* row = dst + (size_t)r * 3072;
    *(uint4*)(row + c0)        = H;
    *(uint4*)(row + 1024 + c0) = H;
    *(uint4*)(row + 2048 + c0) = L;
}

// ===========================================================================
// Weight split+transpose (all 4 weights in one launch): W[1024k,1024n]->B'[n][3072]
// ===========================================================================
__global__ __launch_bounds__(256) void k_wsplit(
    const float* __restrict__ W0, const float* __restrict__ W1,
    const float* __restrict__ W2, const float* __restrict__ W3)
{
    const int slot = blockIdx.z;
    const float* W = (slot == 0) ? W0 : (slot == 1) ? W1 : (slot == 2) ? W2 : W3;
    __nv_bfloat16* dst = (slot < 3) ? (g_Bqkv + (size_t)slot * 1024 * 3072) : g_Bo;
    int nl = blockIdx.x * 256 + threadIdx.x;
    int k0 = blockIdx.y << 3;
    uint4 H, L;
    uint32_t hu[4], lu[4];
#pragma unroll
    for (int i = 0; i < 4; i++) {
        float f0 = W[(size_t)(k0 + 2*i)     * 1024 + nl];
        float f1 = W[(size_t)(k0 + 2*i + 1) * 1024 + nl];
        __nv_bfloat16 h0 = __float2bfloat16(f0);
        __nv_bfloat16 h1 = __float2bfloat16(f1);
        __nv_bfloat16 l0 = __float2bfloat16(f0 - __bfloat162float(h0));
        __nv_bfloat16 l1 = __float2bfloat16(f1 - __bfloat162float(h1));
        hu[i] = pk2(h0, h1); lu[i] = pk2(l0, l1);
    }
    H.x = hu[0]; H.y = hu[1]; H.z = hu[2]; H.w = hu[3];
    L.x = lu[0]; L.y = lu[1]; L.z = lu[2]; L.w = lu[3];
    __nv_bfloat16* row = dst + (size_t)nl * 3072;
    *(uint4*)(row + k0)        = H;
    *(uint4*)(row + 1024 + k0) = L;
    *(uint4*)(row + 2048 + k0) = H;
}

// ===========================================================================
// EK split: fp32 [i,j,64] -> ekh/ekl bf16 (elementwise)
// ===========================================================================
__global__ __launch_bounds__(256) void k_split_ek(const float* __restrict__ EK)
{
    size_t base = ((size_t)blockIdx.x * 256 + threadIdx.x) * 8;
    float4 v0 = *(const float4*)(EK + base);
    float4 v1 = *(const float4*)(EK + base + 4);
    float f[8] = {v0.x, v0.y, v0.z, v0.w, v1.x, v1.y, v1.z, v1.w};
    uint4 H, L;
    uint32_t hu[4], lu[4];
#pragma unroll
    for (int i = 0; i < 4; i++) {
        __nv_bfloat16 h0 = __float2bfloat16(f[2*i]);
        __nv_bfloat16 h1 = __float2bfloat16(f[2*i+1]);
        __nv_bfloat16 l0 = __float2bfloat16(f[2*i]   - __bfloat162float(h0));
        __nv_bfloat16 l1 = __float2bfloat16(f[2*i+1] - __bfloat162float(h1));
        hu[i] = pk2(h0, h1); lu[i] = pk2(l0, l1);
    }
    H.x = hu[0]; H.y = hu[1]; H.z = hu[2]; H.w = hu[3];
    L.x = lu[0]; L.y = lu[1]; L.z = lu[2]; L.w = lu[3];
    *(uint4*)(ekh + base) = H;
    *(uint4*)(ekl + base) = L;
}

// ===========================================================================
// EV transpose-split: fp32 [i,j,64] -> evth/evtl bf16 [i,64,512]
// grid (jt=16, dt=2, i=512), 256 threads, 32x32 smem tile
// ===========================================================================
__global__ __launch_bounds__(256) void k_split_evt(const float* __restrict__ EV)
{
    __shared__ float ts[32][33];
    const int jt = blockIdx.x, dt = blockIdx.y, i = blockIdx.z;
    const int t = threadIdx.x;
    const int r = t >> 3, c0 = (t & 7) << 2;

    float4 v = *(const float4*)(EV + ((size_t)(i * SS_ + jt * 32 + r)) * DKV + dt * 32 + c0);
    ts[r][c0 + 0] = v.x; ts[r][c0 + 1] = v.y;
    ts[r][c0 + 2] = v.z; ts[r][c0 + 3] = v.w;
    __syncthreads();

    // write row d = dt*32 + r, cols j = jt*32 + c0..c0+3
    uint32_t hu[2], lu[2];
#pragma unroll
    for (int p = 0; p < 2; p++) {
        float f0 = ts[c0 + 2*p][r];
        float f1 = ts[c0 + 2*p + 1][r];
        __nv_bfloat16 h0 = __float2bfloat16(f0);
        __nv_bfloat16 h1 = __float2bfloat16(f1);
        __nv_bfloat16 l0 = __float2bfloat16(f0 - __bfloat162float(h0));
        __nv_bfloat16 l1 = __float2bfloat16(f1 - __bfloat162float(h1));
        hu[p] = pk2(h0, h1); lu[p] = pk2(l0, l1);
    }
    size_t off = ((size_t)i * DKV + dt * 32 + r) * SS_ + jt * 32 + c0;
    *(uint2*)(evth + off) = make_uint2(hu[0], hu[1]);
    *(uint2*)(evtl + off) = make_uint2(lu[0], lu[1]);
}

// ===========================================================================
// bf16 mma.sync GEMM (projections): C[4096,N] = A'[4096,3072] @ B'[N,3072]^T
// mode 0: QKV -> q/k splits + transposed-v splits (+biases)
// mode 1: OUT -> outp (+bo)
// ===========================================================================
#define KTOT   3072
#define NCHUNK 96
#define TILEB  (128 * LDS_ * 2)   // 10240

__global__ __launch_bounds__(256) void k_gemm_bf16(
    const float* __restrict__ b0p, const float* __restrict__ b1p,
    const float* __restrict__ b2p, float* __restrict__ outp, int mode)
{
    __shared__ __align__(16) char smem[2 * 2 * TILEB];

    const int tid  = threadIdx.x;
    const int wid  = tid >> 5, lane = tid & 31;
    const int wm   = wid >> 2, wn = wid & 3;
    const int m0   = blockIdx.y * 128, n0 = blockIdx.x * 128;
    const uint32_t sbase = s2u(smem);

    const __nv_bfloat16* __restrict__ Ag = mode ? g_Actx : g_A;
    const __nv_bfloat16* __restrict__ Bg = mode ? g_Bo   : g_Bqkv;

    const int lrow0 = tid >> 2;
    const int lseg  = (tid & 3) << 3;

    float acc[4][4][4];
#pragma unroll
    for (int i = 0; i < 4; i++)
#pragma unroll
        for (int j = 0; j < 4; j++)
#pragma unroll
            for (int q = 0; q < 4; q++) acc[i][j][q] = 0.f;

    {
        uint32_t dA = sbase, dB = sbase + TILEB;
#pragma unroll
        for (int u = 0; u < 2; u++) {
            int row = lrow0 + u * 64;
            CP_ASYNC16(dA + (row * LDS_ + lseg) * 2,
                       Ag + (size_t)(m0 + row) * KTOT + lseg);
            CP_ASYNC16(dB + (row * LDS_ + lseg) * 2,
                       Bg + (size_t)(n0 + row) * KTOT + lseg);
        }
        CP_COMMIT();
    }

    for (int c = 0; c < NCHUNK; c++) {
        CP_WAIT0();
        __syncthreads();

        if (c + 1 < NCHUNK) {
            uint32_t dA = sbase + ((c + 1) & 1) * 2 * TILEB;
            uint32_t dB = dA + TILEB;
            const int koff = (c + 1) * 32 + lseg;
#pragma unroll
            for (int u = 0; u < 2; u++) {
                int row = lrow0 + u * 64;
                CP_ASYNC16(dA + (row * LDS_ + lseg) * 2,
                           Ag + (size_t)(m0 + row) * KTOT + koff);
                CP_ASYNC16(dB + (row * LDS_ + lseg) * 2,
                           Bg + (size_t)(n0 + row) * KTOT + koff);
            }
            CP_COMMIT();
        }

        const uint32_t bufA = sbase + (c & 1) * 2 * TILEB;
        const uint32_t bufB = bufA + TILEB;
        const int lr = lane & 15, lc = (lane >> 4) << 3;

#pragma unroll
        for (int ks = 0; ks < 2; ks++) {
            uint32_t a[4][4];
#pragma unroll
            for (int mi = 0; mi < 4; mi++) {
                uint32_t addr = bufA +
                    ((wm * 64 + mi * 16 + lr) * LDS_ + ks * 16 + lc) * 2;
                LDMATX4(a[mi][0], a[mi][1], a[mi][2], a[mi][3], addr);
            }
            uint32_t b[4][2];
#pragma unroll
            for (int ni2 = 0; ni2 < 2; ni2++) {
                uint32_t r0, r1, r2, r3;
                uint32_t addr = bufB +
                    ((wn * 32 + ni2 * 16 + lr) * LDS_ + ks * 16 + lc) * 2;
                LDMATX4(r0, r1, r2, r3, addr);
                b[2 * ni2][0] = r0;     b[2 * ni2][1] = r2;
                b[2 * ni2 + 1][0] = r1; b[2 * ni2 + 1][1] = r3;
            }
#pragma unroll
            for (int mi = 0; mi < 4; mi++)
#pragma unroll
                for (int ni = 0; ni < 4; ni++)
                    MMA16816(acc[mi][ni], a[mi], b[ni]);
        }
        __syncthreads();
    }

    // -------- epilogue --------
    const int g  = lane >> 2;
    const int tc = (lane & 3) << 1;

    if (mode == 0) {
        const int proj = n0 >> 10;
        const float* bias = (proj == 0) ? b0p : (proj == 1) ? b1p : b2p;
#pragma unroll
        for (int mi = 0; mi < 4; mi++) {
            int m = m0 + wm * 64 + mi * 16 + g;
            int b_ = m >> 9, s_ = m & 511;
            int s2 = s_ + 8;          // same b_ (16-row blocks never straddle 512)
#pragma unroll
            for (int ni = 0; ni < 4; ni++) {
                int nl = (n0 & 1023) + wn * 32 + ni * 8 + tc;
                int hd = nl >> 6, d = nl & 63;
                int bh_ = b_ * HH + hd;
                float x0 = acc[mi][ni][0] + bias[nl];
                float x1 = acc[mi][ni][1] + bias[nl + 1];
                float x2 = acc[mi][ni][2] + bias[nl];
                float x3 = acc[mi][ni][3] + bias[nl + 1];
                __nv_bfloat16 hb0 = __float2bfloat16(x0), lb0 = __float2bfloat16(x0 - __bfloat162float(hb0));
                __nv_bfloat16 hb1 = __float2bfloat16(x1), lb1 = __float2bfloat16(x1 - __bfloat162float(hb1));
                __nv_bfloat16 hb2 = __float2bfloat16(x2), lb2 = __float2bfloat16(x2 - __bfloat162float(hb2));
                __nv_bfloat16 hb3 = __float2bfloat16(x3), lb3 = __float2bfloat16(x3 - __bfloat162float(hb3));
                if (proj < 2) {
                    __nv_bfloat16* ah = (proj == 0) ? qh : kh;
                    __nv_bfloat16* al = (proj == 0) ? ql : kl;
                    size_t o0 = ((size_t)bh_ * SS_ + s_) * DKV + d;
                    size_t o1 = o0 + 8 * DKV;
                    *(uint32_t*)(ah + o0) = pk2(hb0, hb1);
                    *(uint32_t*)(al + o0) = pk2(lb0, lb1);
                    *(uint32_t*)(ah + o1) = pk2(hb2, hb3);
                    *(uint32_t*)(al + o1) = pk2(lb2, lb3);
                } else {
                    size_t o = (size_t)bh_ * DKV * SS_ + (size_t)d * SS_;
                    vth[o + s_]       = hb0;  vtl[o + s_]       = lb0;
                    vth[o + SS_ + s_] = hb1;  vtl[o + SS_ + s_] = lb1;
                    vth[o + s2]       = hb2;  vtl[o + s2]       = lb2;
                    vth[o + SS_ + s2] = hb3;  vtl[o + SS_ + s2] = lb3;
                }
            }
        }
    } else {
#pragma unroll
        for (int mi = 0; mi < 4; mi++) {
            int m = m0 + wm * 64 + mi * 16 + g;
#pragma unroll
            for (int ni = 0; ni < 4; ni++) {
                int ncol = n0 + wn * 32 + ni * 8 + tc;
                float2 o0 = {acc[mi][ni][0] + b0p[ncol],
                             acc[mi][ni][1] + b0p[ncol + 1]};
                float2 o1 = {acc[mi][ni][2] + b0p[ncol],
                             acc[mi][ni][3] + b0p[ncol + 1]};
                *(float2*)(outp + (size_t)m * DM + ncol) = o0;
                *(float2*)(outp + (size_t)(m + 8) * DM + ncol) = o1;
            }
        }
    }
}

// ===========================================================================
// Scores GEMM (3-term bf16, 128x128 CTA, K=64 per term, 6 chunks of 32)
// mode 0 (content): grid(4 jt, 4 it, 128 bh): g_sc = acc*SCALE + bias  (write)
// mode 1 (edge):    grid(4 jt, 512 i):        g_sc += acc*SCALE        (RMW)
// ===========================================================================
__global__ __launch_bounds__(256) void k_scores(const float* __restrict__ bias, int mode)
{
    __shared__ __align__(16) char smem[2 * 2 * TILEB];
    const int tid = threadIdx.x, wid = tid >> 5, lane = tid & 31;
    const int wm = wid >> 2, wn = wid & 3;
    const int j0 = blockIdx.x * 128;

    const __nv_bfloat16 *A0, *A1, *B0, *B1;
    size_t rsA;
    int i0 = 0, bh = 0, iE = 0;
    if (mode == 0) {
        i0 = blockIdx.y * 128; bh = blockIdx.z;
        A0 = qh + ((size_t)bh * SS_ + i0) * DKV;
        A1 = ql + ((size_t)bh * SS_ + i0) * DKV;
        B0 = kh + ((size_t)bh * SS_ + j0) * DKV;
        B1 = kl + ((size_t)bh * SS_ + j0) * DKV;
        rsA = DKV;
    } else {
        iE = blockIdx.y;
        A0 = qh + (size_t)iE * DKV;
        A1 = ql + (size_t)iE * DKV;
        B0 = ekh + ((size_t)iE * SS_ + j0) * DKV;
        B1 = ekl + ((size_t)iE * SS_ + j0) * DKV;
        rsA = (size_t)SS_ * DKV;
    }
    const __nv_bfloat16* At[3] = {A0, A0, A1};
    const __nv_bfloat16* Bt[3] = {B0, B1, B0};

    const uint32_t sbase = s2u(smem);
    const int lrow0 = tid >> 2, lseg = (tid & 3) << 3;

    float acc[4][4][4];
#pragma unroll
    for (int i = 0; i < 4; i++)
#pragma unroll
        for (int j = 0; j < 4; j++)
#pragma unroll
            for (int q = 0; q < 4; q++) acc[i][j][q] = 0.f;

    {
        uint32_t dA = sbase, dB = sbase + TILEB;
#pragma unroll
        for (int u = 0; u < 2; u++) {
            int row = lrow0 + u * 64;
            CP_ASYNC16(dA + (row * LDS_ + lseg) * 2, At[0] + (size_t)row * rsA + lseg);
            CP_ASYNC16(dB + (row * LDS_ + lseg) * 2, Bt[0] + (size_t)row * DKV + lseg);
        }
        CP_COMMIT();
    }

    for (int c = 0; c < 6; c++) {
        CP_WAIT0();
        __syncthreads();

        if (c + 1 < 6) {
            int t2 = (c + 1) >> 1, ko2 = ((c + 1) & 1) * 32;
            uint32_t dA = sbase + ((c + 1) & 1) * 2 * TILEB;
            uint32_t dB = dA + TILEB;
#pragma unroll
            for (int u = 0; u < 2; u++) {
                int row = lrow0 + u * 64;
                CP_ASYNC16(dA + (row * LDS_ + lseg) * 2, At[t2] + (size_t)row * rsA + ko2 + lseg);
                CP_ASYNC16(dB + (row * LDS_ + lseg) * 2, Bt[t2] + (size_t)row * DKV + ko2 + lseg);
            }
            CP_COMMIT();
        }

        const uint32_t bufA = sbase + (c & 1) * 2 * TILEB;
        const uint32_t bufB = bufA + TILEB;
        const int lr = lane & 15, lc = (lane >> 4) << 3;

#pragma unroll
        for (int ks = 0; ks < 2; ks++) {
            uint32_t a[4][4];
#pragma unroll
            for (int mi = 0; mi < 4; mi++) {
                uint32_t addr = bufA + ((wm * 64 + mi * 16 + lr) * LDS_ + ks * 16 + lc) * 2;
                LDMATX4(a[mi][0], a[mi][1], a[mi][2], a[mi][3], addr);
            }
            uint32_t b[4][2];
#pragma unroll
            for (int ni2 = 0; ni2 < 2; ni2++) {
                uint32_t r0, r1, r2, r3;
                uint32_t addr = bufB + ((wn * 32 + ni2 * 16 + lr) * LDS_ + ks * 16 + lc) * 2;
                LDMATX4(r0, r1, r2, r3, addr);
                b[2 * ni2][0] = r0;     b[2 * ni2][1] = r2;
                b[2 * ni2 + 1][0] = r1; b[2 * ni2 + 1][1] = r3;
            }
#pragma unroll
            for (int mi = 0; mi < 4; mi++)
#pragma unroll
                for (int ni = 0; ni < 4; ni++)
                    MMA16816(acc[mi][ni], a[mi], b[ni]);
        }
        __syncthreads();
    }

    const int g = lane >> 2, tc = (lane & 3) << 1;
#pragma unroll
    for (int mi = 0; mi < 4; mi++) {
        int m = wm * 64 + mi * 16 + g;
#pragma unroll
        for (int ni = 0; ni < 4; ni++) {
            int jc = j0 + wn * 32 + ni * 8 + tc;
            if (mode == 0) {
                size_t base0 = ((size_t)bh * SS_ + (i0 + m)) * SS_ + jc;
                size_t base1 = base0 + 8 * SS_;
                float2 o0 = {acc[mi][ni][0] * SCALE + bias[base0],
                             acc[mi][ni][1] * SCALE + bias[base0 + 1]};
                float2 o1 = {acc[mi][ni][2] * SCALE + bias[base1],
                             acc[mi][ni][3] * SCALE + bias[base1 + 1]};
                *(float2*)(g_sc + base0) = o0;
                *(float2*)(g_sc + base1) = o1;
            } else {
                size_t base0 = ((size_t)m * SS_ + iE) * SS_ + jc;
                size_t base1 = base0 + (size_t)8 * SS_ * SS_;
                float2 p0 = *(float2*)(g_sc + base0);
                float2 p1 = *(float2*)(g_sc + base1);
                p0.x += acc[mi][ni][0] * SCALE; p0.y += acc[mi][ni][1] * SCALE;
                p1.x += acc[mi][ni][2] * SCALE; p1.y += acc[mi][ni][3] * SCALE;
                *(float2*)(g_sc + base0) = p0;
                *(float2*)(g_sc + base1) = p1;
            }
        }
    }
}

// ===========================================================================
// Softmax + split: read fp32 scores row, write wh/wl bf16
// ===========================================================================
__global__ __launch_bounds__(256) void k_softmax_split()
{
    const int warp = threadIdx.x >> 5, lane = threadIdx.x & 31;
    const size_t row = (size_t)blockIdx.x * 8 + warp;
    const float* p = g_sc + row * SS_;

    float4 v[4];
    float mx = -1e30f;
#pragma unroll
    for (int w = 0; w < 4; w++) {
        v[w] = *(const float4*)(p + w * 128 + lane * 4);
        mx = fmaxf(mx, fmaxf(fmaxf(v[w].x, v[w].y), fmaxf(v[w].z, v[w].w)));
    }
#pragma unroll
    for (int o = 16; o > 0; o >>= 1) mx = fmaxf(mx, __shfl_xor_sync(~0u, mx, o));

    float sum = 0.f;
#pragma unroll
    for (int w = 0; w < 4; w++) {
        v[w].x = __expf(v[w].x - mx); v[w].y = __expf(v[w].y - mx);
        v[w].z = __expf(v[w].z - mx); v[w].w = __expf(v[w].w - mx);
        sum += v[w].x + v[w].y + v[w].z + v[w].w;
    }
#pragma unroll
    for (int o = 16; o > 0; o >>= 1) sum += __shfl_xor_sync(~0u, sum, o);
    float r = 1.f / sum;
#pragma unroll
    for (int w = 0; w < 4; w++) {
        float f[4] = {v[w].x * r, v[w].y * r, v[w].z * r, v[w].w * r};
        uint32_t hu[2], lu[2];
#pragma unroll
        for (int pq = 0; pq < 2; pq++) {
            __nv_bfloat16 h0 = __float2bfloat16(f[2*pq]);
            __nv_bfloat16 h1 = __float2bfloat16(f[2*pq+1]);
            __nv_bfloat16 l0 = __float2bfloat16(f[2*pq]   - __bfloat162float(h0));
            __nv_bfloat16 l1 = __float2bfloat16(f[2*pq+1] - __bfloat162float(h1));
            hu[pq] = pk2(h0, h1); lu[pq] = pk2(l0, l1);
        }
        size_t off = row * SS_ + w * 128 + lane * 4;
        *(uint2*)(wh + off) = make_uint2(hu[0], hu[1]);
        *(uint2*)(wl + off) = make_uint2(lu[0], lu[1]);
    }
}

// ===========================================================================
// Context GEMM (3-term bf16, 128x64 CTA, K=512 per term, 48 chunks of 32)
// mode 0 (content): grid(4 it, 128 bh): g_ctx = acc  (write)
// mode 1 (edge):    grid(512 i):        g_ctx += acc (RMW)
// warps: 4(m) x 2(n), warp tile 32x32
// ===========================================================================
#define CT_A_TILEB (128 * LDS_ * 2)   // 10240
#define CT_B_TILEB (64 * LDS_ * 2)    // 5120
#define CT_STAGE   (CT_A_TILEB + CT_B_TILEB)

__global__ __launch_bounds__(256) void k_ctx(int mode)
{
    __shared__ __align__(16) char smem[2 * CT_STAGE];
    const int tid = threadIdx.x, wid = tid >> 5, lane = tid & 31;
    const int wm = wid >> 1, wn = wid & 1;

    const __nv_bfloat16 *A0, *A1, *B0, *B1;
    size_t rsA;
    int i0 = 0, bh = 0, iE = 0;
    if (mode == 0) {
        bh = blockIdx.y; i0 = blockIdx.x * 128;
        A0 = wh + (size_t)bh * SS_ * SS_ + (size_t)i0 * SS_;
        A1 = wl + (size_t)bh * SS_ * SS_ + (size_t)i0 * SS_;
        B0 = vth + (size_t)bh * DKV * SS_;
        B1 = vtl + (size_t)bh * DKV * SS_;
        rsA = SS_;
    } else {
        iE = blockIdx.x;
        A0 = wh + (size_t)iE * SS_;
        A1 = wl + (size_t)iE * SS_;
        B0 = evth + (size_t)iE * DKV * SS_;
        B1 = evtl + (size_t)iE * DKV * SS_;
        rsA = (size_t)SS_ * SS_;
    }
    const __nv_bfloat16* At[3] = {A0, A0, A1};
    const __nv_bfloat16* Bt[3] = {B0, B1, B0};

    const uint32_t sbase = s2u(smem);
    const int arow = tid >> 1, aseg = (tid & 1) << 4;   // A: 2 cp16 per thread
    const int brow = tid >> 2, bseg = (tid & 3) << 3;   // B: 1 cp16 per thread

    float acc[2][4][4];
#pragma unroll
    for (int i = 0; i < 2; i++)
#pragma unroll
        for (int j = 0; j < 4; j++)
#pragma unroll
            for (int q = 0; q < 4; q++) acc[i][j][q] = 0.f;

    {
        uint32_t dA = sbase, dB = sbase + CT_A_TILEB;
        CP_ASYNC16(dA + (arow * LDS_ + aseg) * 2,     At[0] + (size_t)arow * rsA + aseg);
        CP_ASYNC16(dA + (arow * LDS_ + aseg + 8) * 2, At[0] + (size_t)arow * rsA + aseg + 8);
        CP_ASYNC16(dB + (brow * LDS_ + bseg) * 2,     Bt[0] + (size_t)brow * SS_ + bseg);
        CP_COMMIT();
    }

    for (int c = 0; c < 48; c++) {
        CP_WAIT0();
        __syncthreads();

        if (c + 1 < 48) {
            int t2 = (c + 1) >> 4, ko2 = ((c + 1) & 15) * 32;
            uint32_t dA = sbase + ((c + 1) & 1) * CT_STAGE;
            uint32_t dB = dA + CT_A_TILEB;
            CP_ASYNC16(dA + (arow * LDS_ + aseg) * 2,     At[t2] + (size_t)arow * rsA + ko2 + aseg);
            CP_ASYNC16(dA + (arow * LDS_ + aseg + 8) * 2, At[t2] + (size_t)arow * rsA + ko2 + aseg + 8);
            CP_ASYNC16(dB + (brow * LDS_ + bseg) * 2,     Bt[t2] + (size_t)brow * SS_ + ko2 + bseg);
            CP_COMMIT();
        }

        const uint32_t bufA = sbase + (c & 1) * CT_STAGE;
        const uint32_t bufB = bufA + CT_A_TILEB;
        const int lr = lane & 15, lc = (lane >> 4) << 3;

#pragma unroll
        for (int ks = 0; ks < 2; ks++) {
            uint32_t a[2][4];
#pragma unroll
            for (int mi = 0; mi < 2; mi++) {
                uint32_t addr = bufA + ((wm * 32 + mi * 16 + lr) * LDS_ + ks * 16 + lc) * 2;
                LDMATX4(a[mi][0], a[mi][1], a[mi][2], a[mi][3], addr);
            }
            uint32_t b[4][2];
#pragma unroll
            for (int ni2 = 0; ni2 < 2; ni2++) {
                uint32_t r0, r1, r2, r3;
                uint32_t addr = bufB + ((wn * 32 + ni2 * 16 + lr) * LDS_ + ks * 16 + lc) * 2;
                LDMATX4(r0, r1, r2, r3, addr);
                b[2 * ni2][0] = r0;     b[2 * ni2][1] = r2;
                b[2 * ni2 + 1][0] = r1; b[2 * ni2 + 1][1] = r3;
            }
#pragma unroll
            for (int mi = 0; mi < 2; mi++)
#pragma unroll
                for (int ni = 0; ni < 4; ni++)
                    MMA16816(acc[mi][ni], a[mi], b[ni]);
        }
        __syncthreads();
    }

    const int g = lane >> 2, tc = (lane & 3) << 1;
#pragma unroll
    for (int mi = 0; mi < 2; mi++) {
        int m = wm * 32 + mi * 16 + g;
#pragma unroll
        for (int ni = 0; ni < 4; ni++) {
            int ncol = wn * 32 + ni * 8 + tc;
            if (mode == 0) {
                int i = i0 + m;
                size_t a0 = ((size_t)(bh >> 4) * SS_ + i) * DM + (bh & 15) * DKV + ncol;
                size_t a1 = a0 + (size_t)8 * DM;
                float2 o0 = {acc[mi][ni][0], acc[mi][ni][1]};
                float2 o1 = {acc[mi][ni][2], acc[mi][ni][3]};
                *(float2*)(g_ctx + a0) = o0;
                *(float2*)(g_ctx + a1) = o1;
            } else {
                int bh0 = m, bh1 = m + 8;
                size_t a0 = ((size_t)(bh0 >> 4) * SS_ + iE) * DM + (bh0 & 15) * DKV + ncol;
                size_t a1 = ((size_t)(bh1 >> 4) * SS_ + iE) * DM + (bh1 & 15) * DKV + ncol;
                float2 p0 = *(float2*)(g_ctx + a0);
                float2 p1 = *(float2*)(g_ctx + a1);
                p0.x += acc[mi][ni][0]; p0.y += acc[mi][ni][1];
                p1.x += acc[mi][ni][2]; p1.y += acc[mi][ni][3];
                *(float2*)(g_ctx + a0) = p0;
                *(float2*)(g_ctx + a1) = p1;
            }
        }
    }
}

// ===========================================================================
// Launcher
// ===========================================================================
extern "C" void kernel_launch(void* const* d_in, const int* in_sizes, int n_in,
                              void* d_out, int out_size)
{
    const float* queries     = (const float*)d_in[0];
    const float* edges_key   = (const float*)d_in[1];
    const float* edges_value = (const float*)d_in[2];
    const float* attn_bias   = (const float*)d_in[3];
    const float* Wq = (const float*)d_in[4];
    const float* bq = (const float*)d_in[5];
    const float* Wk = (const float*)d_in[6];
    const float* bk = (const float*)d_in[7];
    const float* Wv = (const float*)d_in[8];
    const float* bv = (const float*)d_in[9];
    const float* Wo = (const float*)d_in[10];
    const float* bo = (const float*)d_in[11];
    float* out = (float*)d_out;

    cudaStream_t st = 0;
    cudaStreamCaptureStatus cs = cudaStreamCaptureStatusNone;
    if (cudaStreamIsCapturing(cudaStreamPerThread, &cs) == cudaSuccess &&
        cs == cudaStreamCaptureStatusActive)
        st = cudaStreamPerThread;

    // conversions
    k_split    <<<2048, 256, 0, st>>>(queries, 0);
    k_wsplit   <<<dim3(4, 128, 4), 256, 0, st>>>(Wq, Wk, Wv, Wo);
    k_split_ek <<<8192, 256, 0, st>>>(edges_key);
    k_split_evt<<<dim3(16, 2, 512), 256, 0, st>>>(edges_value);

    // QKV projection -> q/k splits + transposed-v splits
    k_gemm_bf16<<<dim3(24, 32), 256, 0, st>>>(bq, bk, bv, nullptr, 0);

    // scores: content (write + bias), then edge (accumulate)
    k_scores<<<dim3(4, 4, 128), 256, 0, st>>>(attn_bias, 0);
    k_scores<<<dim3(4, 512),    256, 0, st>>>(nullptr, 1);

    // softmax -> bf16 split weights
    k_softmax_split<<<8192, 256, 0, st>>>();

    // context: content (write), then edge (accumulate)
    k_ctx<<<dim3(4, 128), 256, 0, st>>>(0);
    k_ctx<<<dim3(512),    256, 0, st>>>(1);

    // output projection
    k_split<<<2048, 256, 0, st>>>(nullptr, 1);
    k_gemm_bf16<<<dim3(8, 32), 256, 0, st>>>(bo, nullptr, nullptr, out, 1);
}